// round 8
// baseline (speedup 1.0000x reference)
#include <cuda_runtime.h>
#include <cuda_bf16.h>
#include <cstdint>

#define NN 50000
#define NR 32
#define DD 64
#define NE_MAX 1600000
#define TILE 128
#define PADMAX (NR * TILE)
#define SA 72          // As row stride (u32): k-paired LDS.64 conflict-free
#define SW 72          // Ws row stride (u32): scalar B LDS conflict-free (8tg+g)
#define FUSED_GRID 592 // 4 blocks/SM

// Relation-sorted edge arrays (+ per-bucket padding to TILE, norm=0)
__device__ int   g_srcS[NE_MAX + PADMAX];
__device__ int   g_dstS[NE_MAX + PADMAX];
__device__ float g_normS[NE_MAX + PADMAX];
__device__ int   g_binCount[NR];
__device__ int   g_cursor[NR];
__device__ int   g_tileRel[NE_MAX / TILE + NR + 2];
__device__ int   g_numTiles;

__device__ __forceinline__ uint32_t f2tf32(float f) {
    uint32_t r;
    asm("cvt.rna.tf32.f32 %0, %1;" : "=r"(r) : "f"(f));
    return r;
}
__device__ __forceinline__ void mma_tf32(float* c, const uint32_t* a, const uint32_t* b) {
    asm volatile(
        "mma.sync.aligned.m16n8k8.row.col.f32.tf32.tf32.f32 "
        "{%0,%1,%2,%3}, {%4,%5,%6,%7}, {%8,%9}, {%0,%1,%2,%3};"
        : "+f"(c[0]), "+f"(c[1]), "+f"(c[2]), "+f"(c[3])
        : "r"(a[0]), "r"(a[1]), "r"(a[2]), "r"(a[3]), "r"(b[0]), "r"(b[1]));
}

// ---------------------------------------------------------------------------
// Sort pass 1: per-relation histogram.
// ---------------------------------------------------------------------------
__global__ void k_hist(const int* __restrict__ rel, int n) {
    __shared__ int sh[NR];
    if (threadIdx.x < NR) sh[threadIdx.x] = 0;
    __syncthreads();
    for (int i = blockIdx.x * blockDim.x + threadIdx.x; i < n;
         i += gridDim.x * blockDim.x)
        atomicAdd(&sh[__ldg(rel + i)], 1);
    __syncthreads();
    if (threadIdx.x < NR) atomicAdd(&g_binCount[threadIdx.x], sh[threadIdx.x]);
}

// ---------------------------------------------------------------------------
// Sort pass 2: TILE-aligned prefix, tile->rel map, in-kernel pad zeroing.
// Launch with 32 threads.
// ---------------------------------------------------------------------------
__global__ void k_prefix() {
    int r = threadIdx.x;
    int cnt = g_binCount[r];
    int tiles = (cnt + TILE - 1) / TILE;
    int t = tiles;
#pragma unroll
    for (int d = 1; d < 32; d <<= 1) {
        int v = __shfl_up_sync(0xFFFFFFFFu, t, d);
        if (r >= d) t += v;
    }
    int tileBase = t - tiles;
    int base = tileBase * TILE;
    g_cursor[r] = base;
    for (int i = 0; i < tiles; i++) g_tileRel[tileBase + i] = r;
    for (int i = base + cnt; i < base + tiles * TILE; i++) {
        g_srcS[i] = 0; g_dstS[i] = 0; g_normS[i] = 0.0f;
    }
    if (r == 31) g_numTiles = t;
}

// ---------------------------------------------------------------------------
// Sort pass 3: scatter edges into relation buckets.
// ---------------------------------------------------------------------------
__global__ void __launch_bounds__(256) k_scatter(const int* __restrict__ src,
                                                 const int* __restrict__ dst,
                                                 const int* __restrict__ rel,
                                                 const float* __restrict__ norm,
                                                 int n) {
    __shared__ int sh_cnt[NR], sh_base[NR], sh_pos[NR];
    const int tid = threadIdx.x;
    if (tid < NR) { sh_cnt[tid] = 0; sh_pos[tid] = 0; }
    __syncthreads();
    const int i = blockIdx.x * 256 + tid;
    int r = 0, s = 0, d = 0;
    float nm = 0.0f;
    const bool ok = i < n;
    if (ok) {
        r = __ldg(rel + i); s = __ldg(src + i);
        d = __ldg(dst + i); nm = __ldg(norm + i);
        atomicAdd(&sh_cnt[r], 1);
    }
    __syncthreads();
    if (tid < NR && sh_cnt[tid] > 0)
        sh_base[tid] = atomicAdd(&g_cursor[tid], sh_cnt[tid]);
    __syncthreads();
    if (ok) {
        int pos = sh_base[r] + atomicAdd(&sh_pos[r], 1);
        g_srcS[pos] = s; g_dstS[pos] = d; g_normS[pos] = nm;
    }
}

// ---------------------------------------------------------------------------
// Fused persistent kernel. Each block walks a CONTIGUOUS run of 128-edge
// tiles (relation-sorted). Ws (current relation's W, tf32) cached in SMEM,
// restaged only on relation change (~1-2 times per block).
// Per tile: gather h[src] -> smem (k-paired, conflict-free STS), then
// 8 K-steps x (2 LDS.64 A-pairs x2mt + 16 scalar B LDS + 16 HMMA),
// epilogue: norm-scale + red.global.add.v2 into out[dst].
// Smem u32: Ws[64*72] | As[128*72] | dst[128] | norm[128]  = 56.3 KB
//  -> 4 blocks/SM (225 KB), ~110 regs, 16 warps/SM.
// ---------------------------------------------------------------------------
__global__ void __launch_bounds__(128) rgcn_fused(const float* __restrict__ h,
                                                  const float* __restrict__ W,
                                                  float* __restrict__ out) {
    extern __shared__ uint32_t smem[];
    uint32_t* Ws     = smem;                       // 64 x 72
    uint32_t* As     = smem + 64 * SW;             // 128 x 72
    int*      s_dst  = (int*)(As + TILE * SA);     // 128
    float*    s_norm = (float*)(s_dst + TILE);     // 128

    const int nT = g_numTiles;
    const int chunk = (nT + (int)gridDim.x - 1) / (int)gridDim.x;
    int t0 = blockIdx.x * chunk;
    int t1 = t0 + chunk; if (t1 > nT) t1 = nT;
    if (t0 >= nT) return;

    const int tid = threadIdx.x, wid = tid >> 5, lane = tid & 31;
    const int g = lane >> 2, tg = lane & 3;
    const int arow = tid >> 3, c = tid & 7;
    const int rot  = (arow & 3) + ((c >> 2) << 2);
    const int wrow = wid * 32;

    int rCur = -1;

    for (int tile = t0; tile < t1; tile++) {
        const int r = g_tileRel[tile];
        if (r != rCur) {
            rCur = r;
            // Stage W_r -> Ws[k][o], tf32, stride 72 (once per relation).
            const float4* Wr = (const float4*)(W + (size_t)r * DD * DD);
#pragma unroll
            for (int j = 0; j < 8; j++) {
                const int idx4 = tid + j * 128;
                const float4 w4 = __ldg(Wr + idx4);
                const int k = idx4 >> 4, o4 = (idx4 & 15) * 4;
                uint32_t* p = &Ws[k * SW + o4];
                p[0] = f2tf32(w4.x); p[1] = f2tf32(w4.y);
                p[2] = f2tf32(w4.z); p[3] = f2tf32(w4.w);
            }
        }

        const int row0 = tile * TILE;
        s_dst[tid]  = g_dstS[row0 + tid];
        s_norm[tid] = g_normS[row0 + tid];

        // Gather A: 8 threads/row, 32B/thread; k-paired slot permute,
        // rotated write order => conflict-free STS.
#pragma unroll
        for (int p = 0; p < 8; p++) {
            const int row = p * 16 + arow;
            const int s = g_srcS[row0 + row];
            const float4* hp = (const float4*)(h + (size_t)s * DD + c * 8);
            const float4 v0 = __ldg(hp), v1 = __ldg(hp + 1);
            const float f[8] = {v0.x, v0.y, v0.z, v0.w, v1.x, v1.y, v1.z, v1.w};
            uint32_t q[8];
#pragma unroll
            for (int t = 0; t < 8; t++)
                q[(t & 3) * 2 + (t >> 2)] = f2tf32(f[t]);
            uint32_t* base = &As[row * SA + c * 8];
#pragma unroll
            for (int s8 = 0; s8 < 8; s8++) {
                const int j = (s8 + rot) & 7;
                base[j] = q[j];
            }
        }
        __syncthreads();

        // Compute: warp tile 32 x 64.
        float acc[2][8][4];
#pragma unroll
        for (int mt = 0; mt < 2; mt++)
#pragma unroll
            for (int nt = 0; nt < 8; nt++)
#pragma unroll
                for (int q = 0; q < 4; q++) acc[mt][nt][q] = 0.0f;

#pragma unroll
        for (int ks = 0; ks < 8; ks++) {
            uint32_t a[2][4];
#pragma unroll
            for (int mt = 0; mt < 2; mt++) {
                const int r0 = wrow + mt * 16 + g;
                const uint2 p0 = *(const uint2*)&As[r0 * SA + ks * 8 + tg * 2];
                const uint2 p1 = *(const uint2*)&As[(r0 + 8) * SA + ks * 8 + tg * 2];
                a[mt][0] = p0.x; a[mt][1] = p1.x; a[mt][2] = p0.y; a[mt][3] = p1.y;
            }
            uint32_t b[8][2];
            const int kA = (ks * 8 + tg) * SW;
            const int kB = kA + 4 * SW;
#pragma unroll
            for (int nt = 0; nt < 8; nt++) {
                b[nt][0] = Ws[kA + nt * 8 + g];
                b[nt][1] = Ws[kB + nt * 8 + g];
            }
#pragma unroll
            for (int mt = 0; mt < 2; mt++)
#pragma unroll
                for (int nt = 0; nt < 8; nt++)
                    mma_tf32(acc[mt][nt], a[mt], b[nt]);
        }

        // Epilogue: scale by norm, red.v2 into out[dst].
#pragma unroll
        for (int mt = 0; mt < 2; mt++) {
            const int lr0 = wrow + mt * 16 + g, lr1 = lr0 + 8;
            const float n0 = s_norm[lr0], n1 = s_norm[lr1];
            float* o0 = out + (size_t)s_dst[lr0] * DD;
            float* o1 = out + (size_t)s_dst[lr1] * DD;
#pragma unroll
            for (int nt = 0; nt < 8; nt++) {
                const int oc = nt * 8 + 2 * tg;
                asm volatile("red.global.add.v2.f32 [%0], {%1, %2};"
                             :: "l"(o0 + oc), "f"(acc[mt][nt][0] * n0),
                                "f"(acc[mt][nt][1] * n0) : "memory");
                asm volatile("red.global.add.v2.f32 [%0], {%1, %2};"
                             :: "l"(o1 + oc), "f"(acc[mt][nt][2] * n1),
                                "f"(acc[mt][nt][3] * n1) : "memory");
            }
        }
        __syncthreads();   // As/dst/norm (and Ws on change) safe to restage
    }
}

// ---------------------------------------------------------------------------
extern "C" void kernel_launch(void* const* d_in, const int* in_sizes, int n_in,
                              void* d_out, int out_size) {
    const float* h    = (const float*)d_in[0];
    const float* W    = (const float*)d_in[1];
    const int*   src  = (const int*)d_in[2];
    const int*   dst  = (const int*)d_in[3];
    const int*   rel  = (const int*)d_in[4];
    const float* norm = (const float*)d_in[5];
    float*       out  = (float*)d_out;

    const int n_edges = in_sizes[2];   // 1600000

    void* p_cnt;
    cudaGetSymbolAddress(&p_cnt, g_binCount);
    cudaMemsetAsync(out,   0, (size_t)out_size * sizeof(float), 0);
    cudaMemsetAsync(p_cnt, 0, sizeof(int) * NR, 0);

    k_hist<<<592, 256>>>(rel, n_edges);
    k_prefix<<<1, 32>>>();
    k_scatter<<<(n_edges + 255) / 256, 256>>>(src, dst, rel, norm, n_edges);

    const int smem_bytes = (64 * SW + TILE * SA + TILE + TILE) * 4;
    static bool attr_set = false;
    if (!attr_set) {
        cudaFuncSetAttribute(rgcn_fused,
                             cudaFuncAttributeMaxDynamicSharedMemorySize,
                             smem_bytes);
        attr_set = true;
    }
    rgcn_fused<<<FUSED_GRID, 128, smem_bytes>>>(h, W, out);
}

// round 9
// speedup vs baseline: 1.2773x; 1.2773x over previous
#include <cuda_runtime.h>
#include <cuda_bf16.h>
#include <cstdint>

#define NN 50000
#define NR 32
#define DD 64
#define NE_MAX 1600000
#define TILE 128
#define PADMAX (NR * TILE)
#define WS_STRIDE 72   // Ws stride: B-fragment scalar LDS conflict-free
#define ASTR 68        // As stride: A-fragment scalar LDS conflict-free
#define ESTR 72        // epilogue stride: STS.64 banks 4g+tg, conflict-free

// Packed relation-sorted edges: (src, dst, norm_bits, 0)
__device__ int4 g_edge[NE_MAX + PADMAX];
__device__ int  g_binCount[NR];
__device__ int  g_cursor[NR];
__device__ int  g_tileRel[NE_MAX / TILE + NR + 2];
__device__ int  g_numTiles;

__device__ __forceinline__ uint32_t f2tf32(float f) {
    uint32_t r;
    asm("cvt.rna.tf32.f32 %0, %1;" : "=r"(r) : "f"(f));
    return r;
}
__device__ __forceinline__ void mma_tf32(float* c, const uint32_t* a, const uint32_t* b) {
    asm volatile(
        "mma.sync.aligned.m16n8k8.row.col.f32.tf32.tf32.f32 "
        "{%0,%1,%2,%3}, {%4,%5,%6,%7}, {%8,%9}, {%0,%1,%2,%3};"
        : "+f"(c[0]), "+f"(c[1]), "+f"(c[2]), "+f"(c[3])
        : "r"(a[0]), "r"(a[1]), "r"(a[2]), "r"(a[3]), "r"(b[0]), "r"(b[1]));
}

// ---------------------------------------------------------------------------
// Sort pass 1: per-relation histogram.
// ---------------------------------------------------------------------------
__global__ void k_hist(const int* __restrict__ rel, int n) {
    __shared__ int sh[NR];
    if (threadIdx.x < NR) sh[threadIdx.x] = 0;
    __syncthreads();
    for (int i = blockIdx.x * blockDim.x + threadIdx.x; i < n;
         i += gridDim.x * blockDim.x)
        atomicAdd(&sh[__ldg(rel + i)], 1);
    __syncthreads();
    if (threadIdx.x < NR) atomicAdd(&g_binCount[threadIdx.x], sh[threadIdx.x]);
}

// ---------------------------------------------------------------------------
// Sort pass 2: TILE-aligned prefix, tile->rel map, pad zeroing. 32 threads.
// ---------------------------------------------------------------------------
__global__ void k_prefix() {
    int r = threadIdx.x;
    int cnt = g_binCount[r];
    int tiles = (cnt + TILE - 1) / TILE;
    int t = tiles;
#pragma unroll
    for (int d = 1; d < 32; d <<= 1) {
        int v = __shfl_up_sync(0xFFFFFFFFu, t, d);
        if (r >= d) t += v;
    }
    int tileBase = t - tiles;
    int base = tileBase * TILE;
    g_cursor[r] = base;
    for (int i = 0; i < tiles; i++) g_tileRel[tileBase + i] = r;
    for (int i = base + cnt; i < base + tiles * TILE; i++)
        g_edge[i] = make_int4(0, 0, 0, 0);
    if (r == 31) g_numTiles = t;
}

// ---------------------------------------------------------------------------
// Sort pass 3: scatter packed edge records into relation buckets.
// ---------------------------------------------------------------------------
__global__ void __launch_bounds__(256) k_scatter(const int* __restrict__ src,
                                                 const int* __restrict__ dst,
                                                 const int* __restrict__ rel,
                                                 const float* __restrict__ norm,
                                                 int n) {
    __shared__ int sh_cnt[NR], sh_base[NR], sh_pos[NR];
    const int tid = threadIdx.x;
    if (tid < NR) { sh_cnt[tid] = 0; sh_pos[tid] = 0; }
    __syncthreads();
    const int i = blockIdx.x * 256 + tid;
    int r = 0, s = 0, d = 0;
    float nm = 0.0f;
    const bool ok = i < n;
    if (ok) {
        r = __ldg(rel + i); s = __ldg(src + i);
        d = __ldg(dst + i); nm = __ldg(norm + i);
        atomicAdd(&sh_cnt[r], 1);
    }
    __syncthreads();
    if (tid < NR && sh_cnt[tid] > 0)
        sh_base[tid] = atomicAdd(&g_cursor[tid], sh_cnt[tid]);
    __syncthreads();
    if (ok) {
        int pos = sh_base[r] + atomicAdd(&sh_pos[r], 1);
        g_edge[pos] = make_int4(s, d, __float_as_int(nm), 0);
    }
}

// ---------------------------------------------------------------------------
// Fused kernel (R5 structure): one 128-edge tile per block.
//   gather h[src] -> smem -> mma.sync tf32 with W[rel] -> smem-transposed
//   coalesced red.global.add.v4 into out[dst].
// Smem u32: Ws[64*72] | As[128*68] | dst[128] | norm[128]  (~53 KB)
// Epilogue reuses [0 .. 128*72) as float with stride 72 (conflict-free).
// ---------------------------------------------------------------------------
__global__ void __launch_bounds__(128) rgcn_fused(const float* __restrict__ h,
                                                  const float* __restrict__ W,
                                                  float* __restrict__ out) {
    extern __shared__ uint32_t smem[];
    uint32_t* Ws     = smem;                      // 64*72
    uint32_t* As     = smem + 64 * WS_STRIDE;     // 128*68
    int*      s_dst  = (int*)(As + 128 * ASTR);   // 128
    float*    s_norm = (float*)(s_dst + 128);     // 128
    float*    E      = (float*)smem;              // epilogue: 128 x 72 (reuse)

    const int tile = blockIdx.x;
    if (tile >= g_numTiles) return;
    const int r    = g_tileRel[tile];
    const int row0 = tile << 7;

    const int tid = threadIdx.x, wid = tid >> 5, lane = tid & 31;
    const int g = lane >> 2, tg = lane & 3;

    {   // meta: one packed record per thread (coalesced LDG.128)
        const int4 e = g_edge[row0 + tid];
        s_dst[tid]  = e.y;
        s_norm[tid] = __int_as_float(e.z);
    }

    // Stage W_r -> tf32 smem [k][o], stride 72
    const float4* Wr = (const float4*)(W + (size_t)r * DD * DD);
#pragma unroll
    for (int j = 0; j < 8; j++) {
        const int idx4 = tid + j * 128;
        const float4 w4 = __ldg(Wr + idx4);
        const int k = idx4 >> 4, o4 = (idx4 & 15) * 4;
        uint32_t* p = &Ws[k * WS_STRIDE + o4];
        p[0] = f2tf32(w4.x); p[1] = f2tf32(w4.y);
        p[2] = f2tf32(w4.z); p[3] = f2tf32(w4.w);
    }

    // Stage A: gather 128 h-rows. 8 threads/row, 32B per thread.
    const int arow = tid >> 3, chunk = tid & 7;
#pragma unroll
    for (int p = 0; p < 8; p++) {
        const int row = p * 16 + arow;
        const int s = ((const int*)&g_edge[row0 + row])[0];   // .x = src
        const float4* hp = (const float4*)(h + (size_t)s * DD + chunk * 8);
        const float4 v0 = __ldg(hp), v1 = __ldg(hp + 1);
        uint32_t* q = &As[row * ASTR + chunk * 8];
        q[0] = f2tf32(v0.x); q[1] = f2tf32(v0.y);
        q[2] = f2tf32(v0.z); q[3] = f2tf32(v0.w);
        q[4] = f2tf32(v1.x); q[5] = f2tf32(v1.y);
        q[6] = f2tf32(v1.z); q[7] = f2tf32(v1.w);
    }
    __syncthreads();

    float acc[2][8][4];
#pragma unroll
    for (int mt = 0; mt < 2; mt++)
#pragma unroll
        for (int nt = 0; nt < 8; nt++)
#pragma unroll
            for (int q = 0; q < 4; q++) acc[mt][nt][q] = 0.0f;

    const int wrow = wid * 32;
#pragma unroll
    for (int ks = 0; ks < 8; ks++) {
        const int k0 = ks * 8 + tg;
        uint32_t a[2][4];
#pragma unroll
        for (int mt = 0; mt < 2; mt++) {
            const int r0 = wrow + mt * 16 + g;
            a[mt][0] = As[r0 * ASTR + k0];
            a[mt][1] = As[(r0 + 8) * ASTR + k0];
            a[mt][2] = As[r0 * ASTR + k0 + 4];
            a[mt][3] = As[(r0 + 8) * ASTR + k0 + 4];
        }
        uint32_t b[8][2];
        const int kA = k0 * WS_STRIDE;
        const int kB = kA + 4 * WS_STRIDE;
#pragma unroll
        for (int nt = 0; nt < 8; nt++) {
            b[nt][0] = Ws[kA + nt * 8 + g];
            b[nt][1] = Ws[kB + nt * 8 + g];
        }
#pragma unroll
        for (int mt = 0; mt < 2; mt++)
#pragma unroll
            for (int nt = 0; nt < 8; nt++)
                mma_tf32(acc[mt][nt], a[mt], b[nt]);
    }

    // --- Epilogue: norm-scale into smem (conflict-free STS.64), then
    //     coalesced red.global.add.v4 (16 lanes per row). ---
    __syncthreads();   // all warps done reading Ws/As before overwrite
#pragma unroll
    for (int mt = 0; mt < 2; mt++) {
        const int lr0 = wrow + mt * 16 + g, lr1 = lr0 + 8;
        const float n0 = s_norm[lr0], n1 = s_norm[lr1];
#pragma unroll
        for (int nt = 0; nt < 8; nt++) {
            const int oc = nt * 8 + 2 * tg;
            *(float2*)&E[lr0 * ESTR + oc] =
                make_float2(acc[mt][nt][0] * n0, acc[mt][nt][1] * n0);
            *(float2*)&E[lr1 * ESTR + oc] =
                make_float2(acc[mt][nt][2] * n1, acc[mt][nt][3] * n1);
        }
    }
    __syncthreads();

    const int erow = tid >> 4, q4 = (tid & 15) * 4;
#pragma unroll
    for (int p = 0; p < 16; p++) {
        const int row = p * 8 + erow;
        const float4 v = *(const float4*)&E[row * ESTR + q4];
        float* o = out + (size_t)s_dst[row] * DD + q4;
        asm volatile("red.global.add.v4.f32 [%0], {%1, %2, %3, %4};"
                     :: "l"(o), "f"(v.x), "f"(v.y), "f"(v.z), "f"(v.w)
                     : "memory");
    }
}

// ---------------------------------------------------------------------------
extern "C" void kernel_launch(void* const* d_in, const int* in_sizes, int n_in,
                              void* d_out, int out_size) {
    const float* h    = (const float*)d_in[0];
    const float* W    = (const float*)d_in[1];
    const int*   src  = (const int*)d_in[2];
    const int*   dst  = (const int*)d_in[3];
    const int*   rel  = (const int*)d_in[4];
    const float* norm = (const float*)d_in[5];
    float*       out  = (float*)d_out;

    const int n_edges = in_sizes[2];   // 1600000

    void* p_cnt;
    cudaGetSymbolAddress(&p_cnt, g_binCount);
    cudaMemsetAsync(out,   0, (size_t)out_size * sizeof(float), 0);
    cudaMemsetAsync(p_cnt, 0, sizeof(int) * NR, 0);

    k_hist<<<592, 256>>>(rel, n_edges);
    k_prefix<<<1, 32>>>();
    k_scatter<<<(n_edges + 255) / 256, 256>>>(src, dst, rel, norm, n_edges);

    const int smem_bytes = (64 * WS_STRIDE + 128 * ASTR + 128 + 128) * 4;
    static bool attr_set = false;
    if (!attr_set) {
        cudaFuncSetAttribute(rgcn_fused,
                             cudaFuncAttributeMaxDynamicSharedMemorySize,
                             smem_bytes);
        attr_set = true;
    }
    const int max_tiles = n_edges / TILE + NR + 1;
    rgcn_fused<<<max_tiles, 128, smem_bytes>>>(h, W, out);
}

// round 10
// speedup vs baseline: 1.3548x; 1.0607x over previous
#include <cuda_runtime.h>
#include <cuda_bf16.h>
#include <cstdint>

#define NN 50000
#define NR 32
#define DD 64
#define NE_MAX 1600000
#define TILE 128
#define PADMAX (NR * TILE)
#define SA  72    // As stride (u32): k-paired LDS.64 frags conflict-free (16-lane phases)
#define SWP 132   // Wp stride (u32): LDS.128 B frags conflict-free (8-lane phases)
#define WP_ROW (32 * SWP)   // 4224 u32 per relation
#define ESTR 72   // epilogue stride

// Packed relation-sorted edges: (src, dst, norm_bits, 0)
__device__ int4     g_edge[NE_MAX + PADMAX];
__device__ int      g_binCount[NR];
__device__ int      g_cursor[NR];
__device__ int      g_tileRel[NE_MAX / TILE + NR + 2];
__device__ int      g_numTiles;
// Precomputed tf32 operands (rounded once, fragment-ready layouts)
__device__ uint32_t g_hT[(size_t)NN * DD];        // h, k-paired slots per row
__device__ uint32_t g_Wp[(size_t)NR * WP_ROW];    // W, mma-fragment permuted

__device__ __forceinline__ uint32_t f2tf32(float f) {
    uint32_t r;
    asm("cvt.rna.tf32.f32 %0, %1;" : "=r"(r) : "f"(f));
    return r;
}
__device__ __forceinline__ void mma_tf32(float* c, const uint32_t* a, const uint32_t* b) {
    asm volatile(
        "mma.sync.aligned.m16n8k8.row.col.f32.tf32.tf32.f32 "
        "{%0,%1,%2,%3}, {%4,%5,%6,%7}, {%8,%9}, {%0,%1,%2,%3};"
        : "+f"(c[0]), "+f"(c[1]), "+f"(c[2]), "+f"(c[3])
        : "r"(a[0]), "r"(a[1]), "r"(a[2]), "r"(a[3]), "r"(b[0]), "r"(b[1]));
}
__device__ __forceinline__ uint32_t smem_u32(const void* p) {
    uint32_t a;
    asm("{ .reg .u64 t; cvta.to.shared.u64 t, %1; cvt.u32.u64 %0, t; }" : "=r"(a) : "l"(p));
    return a;
}
__device__ __forceinline__ void cp16(uint32_t saddr, const void* gaddr) {
    asm volatile("cp.async.ca.shared.global [%0], [%1], 16;"
                 :: "r"(saddr), "l"(gaddr) : "memory");
}
#define CP_COMMIT() asm volatile("cp.async.commit_group;" ::: "memory")
#define CP_WAIT0()  asm volatile("cp.async.wait_group 0;" ::: "memory")

// ---------------------------------------------------------------------------
// Preamble: histogram / prefix / scatter (counting sort by relation)
// ---------------------------------------------------------------------------
__global__ void k_hist(const int* __restrict__ rel, int n) {
    __shared__ int sh[NR];
    if (threadIdx.x < NR) sh[threadIdx.x] = 0;
    __syncthreads();
    for (int i = blockIdx.x * blockDim.x + threadIdx.x; i < n;
         i += gridDim.x * blockDim.x)
        atomicAdd(&sh[__ldg(rel + i)], 1);
    __syncthreads();
    if (threadIdx.x < NR) atomicAdd(&g_binCount[threadIdx.x], sh[threadIdx.x]);
}

__global__ void k_prefix() {   // 32 threads
    int r = threadIdx.x;
    int cnt = g_binCount[r];
    int tiles = (cnt + TILE - 1) / TILE;
    int t = tiles;
#pragma unroll
    for (int d = 1; d < 32; d <<= 1) {
        int v = __shfl_up_sync(0xFFFFFFFFu, t, d);
        if (r >= d) t += v;
    }
    int tileBase = t - tiles;
    int base = tileBase * TILE;
    g_cursor[r] = base;
    for (int i = 0; i < tiles; i++) g_tileRel[tileBase + i] = r;
    for (int i = base + cnt; i < base + tiles * TILE; i++)
        g_edge[i] = make_int4(0, 0, 0, 0);
    if (r == 31) g_numTiles = t;
}

__global__ void __launch_bounds__(256) k_scatter(const int* __restrict__ src,
                                                 const int* __restrict__ dst,
                                                 const int* __restrict__ rel,
                                                 const float* __restrict__ norm,
                                                 int n) {
    __shared__ int sh_cnt[NR], sh_base[NR], sh_pos[NR];
    const int tid = threadIdx.x;
    if (tid < NR) { sh_cnt[tid] = 0; sh_pos[tid] = 0; }
    __syncthreads();
    const int i = blockIdx.x * 256 + tid;
    int r = 0, s = 0, d = 0;
    float nm = 0.0f;
    const bool ok = i < n;
    if (ok) {
        r = __ldg(rel + i); s = __ldg(src + i);
        d = __ldg(dst + i); nm = __ldg(norm + i);
        atomicAdd(&sh_cnt[r], 1);
    }
    __syncthreads();
    if (tid < NR && sh_cnt[tid] > 0)
        sh_base[tid] = atomicAdd(&g_cursor[tid], sh_cnt[tid]);
    __syncthreads();
    if (ok) {
        int pos = sh_base[r] + atomicAdd(&sh_pos[r], 1);
        g_edge[pos] = make_int4(s, d, __float_as_int(nm), 0);
    }
}

// ---------------------------------------------------------------------------
// Preamble: convert h and W to tf32 in fragment-ready layouts (rounded once).
//   h:  slot(k) = (k>>3)*8 + (k&3)*2 + ((k>>2)&1)        (k-paired for LDS.64)
//   W:  Wp[kp][col*2+half], kp=(k>>3)*4+(k&3), half=(k>>2)&1,
//       col=(o&7)*8+(o>>3)                               (uint4 B frags)
// ---------------------------------------------------------------------------
__global__ void __launch_bounds__(256) k_convert(const float* __restrict__ h,
                                                 const float* __restrict__ W) {
    const int i = blockIdx.x * 256 + threadIdx.x;
    if (i < NN * DD) {
        const int n = i >> 6, k = i & 63;
        const int slot = (k >> 3) * 8 + (k & 3) * 2 + ((k >> 2) & 1);
        g_hT[(n << 6) + slot] = f2tf32(__ldg(h + i));
    }
    if (i < NR * DD * DD) {
        const int r = i >> 12, rem = i & 4095, k = rem >> 6, o = rem & 63;
        const int kp = (k >> 3) * 4 + (k & 3), half = (k >> 2) & 1;
        const int col = (o & 7) * 8 + (o >> 3);
        g_Wp[(size_t)r * WP_ROW + kp * SWP + col * 2 + half] = f2tf32(__ldg(W + i));
    }
}

// ---------------------------------------------------------------------------
// Fused kernel: one 128-edge tile per block.
//   cp.async stage (W fragment-image + gathered h rows) -> mma.sync tf32
//   (LDS.64 A frags, LDS.128 B frags) -> smem-transposed coalesced red.v4.
// Smem u32: Wp[32*132] | As[128*72] | dst[128] | norm[128] = 53.5 KB
//  -> 4 blocks/SM. Epilogue reuses smem[0..128*72) as float stride 72.
// ---------------------------------------------------------------------------
__global__ void __launch_bounds__(128) rgcn_fused(float* __restrict__ out) {
    extern __shared__ uint32_t smem[];
    uint32_t* Wp     = smem;                       // 4224
    uint32_t* As     = smem + WP_ROW;              // 9216
    int*      s_dst  = (int*)(As + TILE * SA);     // 128
    float*    s_norm = (float*)(s_dst + TILE);     // 128
    float*    E      = (float*)smem;               // epilogue overlay

    const int tile = blockIdx.x;
    if (tile >= g_numTiles) return;
    const int r    = g_tileRel[tile];
    const int row0 = tile << 7;

    const int tid = threadIdx.x, wid = tid >> 5, lane = tid & 31;
    const int g = lane >> 2, tg = lane & 3;

    {   // meta: one packed record per thread (coalesced LDG.128)
        const int4 e = g_edge[row0 + tid];
        s_dst[tid]  = e.y;
        s_norm[tid] = __int_as_float(e.z);
    }

    // Stage W fragment-image: 4224 u32 = 1056 x 16B chunks.
    {
        const uint32_t* wg = g_Wp + (size_t)r * WP_ROW;
        const uint32_t wsm = smem_u32(Wp);
#pragma unroll
        for (int j = 0; j < 9; j++) {
            const int idx = j * 128 + tid;
            if (idx < 1056) cp16(wsm + idx * 16, wg + idx * 4);
        }
    }
    // Stage A: gather 128 h-rows (k-paired tf32), 16 threads/row x 16B.
    {
        const int arow = tid >> 4, c = tid & 15;
        const uint32_t asm_base = smem_u32(As);
#pragma unroll
        for (int p = 0; p < 16; p++) {
            const int row = p * 8 + arow;
            const int s = ((const int*)g_edge)[(size_t)(row0 + row) * 4];  // .x
            cp16(asm_base + (row * SA + c * 4) * 4,
                 g_hT + ((size_t)s << 6) + c * 4);
        }
    }
    CP_COMMIT();
    CP_WAIT0();
    __syncthreads();

    // Mainloop: warp tile 32 x 64.
    float acc[2][8][4];
#pragma unroll
    for (int mt = 0; mt < 2; mt++)
#pragma unroll
        for (int nt = 0; nt < 8; nt++)
#pragma unroll
            for (int q = 0; q < 4; q++) acc[mt][nt][q] = 0.0f;

    const int wrow = wid * 32;
#pragma unroll
    for (int ks = 0; ks < 8; ks++) {
        uint32_t a[2][4];
#pragma unroll
        for (int mt = 0; mt < 2; mt++) {
            const int r0 = wrow + mt * 16 + g;
            const uint2 p0 = *(const uint2*)&As[r0 * SA + ks * 8 + tg * 2];
            const uint2 p1 = *(const uint2*)&As[(r0 + 8) * SA + ks * 8 + tg * 2];
            a[mt][0] = p0.x; a[mt][1] = p1.x; a[mt][2] = p0.y; a[mt][3] = p1.y;
        }
        uint32_t b[8][2];
        const uint32_t* brow = &Wp[(ks * 4 + tg) * SWP + g * 16];
#pragma unroll
        for (int m = 0; m < 4; m++) {
            const uint4 bb = *(const uint4*)(brow + m * 4);
            b[2 * m][0]     = bb.x; b[2 * m][1]     = bb.y;
            b[2 * m + 1][0] = bb.z; b[2 * m + 1][1] = bb.w;
        }
#pragma unroll
        for (int mt = 0; mt < 2; mt++)
#pragma unroll
            for (int nt = 0; nt < 8; nt++)
                mma_tf32(acc[mt][nt], a[mt], b[nt]);
    }

    // Epilogue: norm-scale into smem, then coalesced red.v4.
    __syncthreads();
#pragma unroll
    for (int mt = 0; mt < 2; mt++) {
        const int lr0 = wrow + mt * 16 + g, lr1 = lr0 + 8;
        const float n0 = s_norm[lr0], n1 = s_norm[lr1];
#pragma unroll
        for (int nt = 0; nt < 8; nt++) {
            const int oc = nt * 8 + 2 * tg;
            *(float2*)&E[lr0 * ESTR + oc] =
                make_float2(acc[mt][nt][0] * n0, acc[mt][nt][1] * n0);
            *(float2*)&E[lr1 * ESTR + oc] =
                make_float2(acc[mt][nt][2] * n1, acc[mt][nt][3] * n1);
        }
    }
    __syncthreads();

    const int erow = tid >> 4, q4 = (tid & 15) * 4;
#pragma unroll
    for (int p = 0; p < 16; p++) {
        const int row = p * 8 + erow;
        const float4 v = *(const float4*)&E[row * ESTR + q4];
        float* o = out + (size_t)s_dst[row] * DD + q4;
        asm volatile("red.global.add.v4.f32 [%0], {%1, %2, %3, %4};"
                     :: "l"(o), "f"(v.x), "f"(v.y), "f"(v.z), "f"(v.w)
                     : "memory");
    }
}

// ---------------------------------------------------------------------------
extern "C" void kernel_launch(void* const* d_in, const int* in_sizes, int n_in,
                              void* d_out, int out_size) {
    const float* h    = (const float*)d_in[0];
    const float* W    = (const float*)d_in[1];
    const int*   src  = (const int*)d_in[2];
    const int*   dst  = (const int*)d_in[3];
    const int*   rel  = (const int*)d_in[4];
    const float* norm = (const float*)d_in[5];
    float*       out  = (float*)d_out;

    const int n_edges = in_sizes[2];   // 1600000

    void* p_cnt;
    cudaGetSymbolAddress(&p_cnt, g_binCount);
    cudaMemsetAsync(out,   0, (size_t)out_size * sizeof(float), 0);
    cudaMemsetAsync(p_cnt, 0, sizeof(int) * NR, 0);

    k_convert<<<(NN * DD + 255) / 256, 256>>>(h, W);
    k_hist<<<592, 256>>>(rel, n_edges);
    k_prefix<<<1, 32>>>();
    k_scatter<<<(n_edges + 255) / 256, 256>>>(src, dst, rel, norm, n_edges);

    const int smem_bytes = (WP_ROW + TILE * SA + TILE + TILE) * 4;
    static bool attr_set = false;
    if (!attr_set) {
        cudaFuncSetAttribute(rgcn_fused,
                             cudaFuncAttributeMaxDynamicSharedMemorySize,
                             smem_bytes);
        attr_set = true;
    }
    const int max_tiles = n_edges / TILE + NR + 1;
    rgcn_fused<<<max_tiles, 128, smem_bytes>>>(out);
}